// round 15
// baseline (speedup 1.0000x reference)
#include <cuda_runtime.h>
#include <cuda_bf16.h>
#include <cfloat>
#include <cmath>
#include <cstdint>

#define BN 64
#define SS 1024
#define EE 512
#define KK 1024
#define AA 128

// ------------------------- device scratch -------------------------
__device__ float g_scores[BN * SS];
__device__ float g_sh[BN * KK];
__device__ __align__(128) __nv_bfloat16 g_states_h[(size_t)BN * SS * EE + 1024]; // +pad for (b=63,s=1023) window
__device__ __align__(128) __nv_bfloat16 g_W1pT[(size_t)KK * KK];                 // [f][k]
__device__ int g_rowmap[BN * SS + 128];   // packed valid rows: value = b*1024 + s
__device__ int g_nrows;                   // number of valid rows L

// ------------------------- helpers -------------------------
__device__ __forceinline__ uint32_t smem_u32(const void* p) {
    uint32_t a;
    asm("{ .reg .u64 t; cvta.to.shared.u64 t, %1; cvt.u32.u64 %0, t; }" : "=r"(a) : "l"(p));
    return a;
}
__device__ __forceinline__ void cp_async16(uint32_t dst, const void* src) {
    asm volatile("cp.async.cg.shared.global [%0], [%1], 16;" :: "r"(dst), "l"(src) : "memory");
}
#define CP_COMMIT() asm volatile("cp.async.commit_group;" ::: "memory")
#define CP_WAIT1()  asm volatile("cp.async.wait_group 1;" ::: "memory")
#define CP_WAIT0()  asm volatile("cp.async.wait_group 0;" ::: "memory")

__device__ __forceinline__ void ldmx4(uint32_t* r, uint32_t addr) {
    asm volatile("ldmatrix.sync.aligned.m8n8.x4.shared.b16 {%0,%1,%2,%3}, [%4];"
        : "=r"(r[0]), "=r"(r[1]), "=r"(r[2]), "=r"(r[3]) : "r"(addr));
}
__device__ __forceinline__ void mma16816(float* c, const uint32_t* a, uint32_t b0, uint32_t b1) {
    asm volatile("mma.sync.aligned.m16n8k16.row.col.f32.bf16.bf16.f32 "
        "{%0,%1,%2,%3}, {%4,%5,%6,%7}, {%8,%9}, {%0,%1,%2,%3};"
        : "+f"(c[0]), "+f"(c[1]), "+f"(c[2]), "+f"(c[3])
        : "r"(a[0]), "r"(a[1]), "r"(a[2]), "r"(a[3]), "r"(b0), "r"(b1));
}

// ---------------------------------------------------------------------------
// Merged prep kernel: blocks [0,64) rowmap | [64,1088) W1p transpose+bf16 |
// [1088, 9280) states->bf16. Each block takes exactly one branch (uniform).
// ---------------------------------------------------------------------------
__global__ __launch_bounds__(256) void prep_kernel(
    const float* __restrict__ states, const float* __restrict__ W1p,
    const int* __restrict__ lengths)
{
    const int bx = blockIdx.x;
    const int tid = threadIdx.x;

    if (bx < 64) {
        // ---- row map ----
        __shared__ int pref[65];
        const int b = bx;
        if (tid == 0) {
            int a = 0; pref[0] = 0;
            for (int i = 0; i < 64; ++i) { a += lengths[i] - 1; pref[i + 1] = a; }
            if (b == 0) g_nrows = a;
        }
        __syncthreads();
        const int p = pref[b], n = pref[b + 1] - p, base = b << 10;
        for (int j = tid; j < n; j += 256) g_rowmap[p + j] = base + j;
        if (b == 63) {
            const int L = pref[64];
            const int Lpad = (L + 127) & ~127;
            for (int j = L + tid; j < Lpad; j += 256) g_rowmap[j] = 0;  // padded rows -> safe row 0
        }
    } else if (bx < 1088) {
        // ---- W1p transpose + bf16 ----
        __shared__ __nv_bfloat16 t[32][33];
        const int c = bx - 64;
        const int txb = c & 31, tyb = c >> 5;     // 32 x 32 tile grid
        const int tx = tid & 31, ty = tid >> 5;   // 32 x 8 threads
        #pragma unroll
        for (int i = 0; i < 4; ++i)
            t[ty + i * 8][tx] = __float2bfloat16(W1p[(size_t)(tyb * 32 + ty + i * 8) * KK + txb * 32 + tx]);
        __syncthreads();
        #pragma unroll
        for (int i = 0; i < 4; ++i)
            g_W1pT[(size_t)(txb * 32 + ty + i * 8) * KK + tyb * 32 + tx] = t[tx][ty + i * 8];
    } else {
        // ---- states -> bf16 (valid rows only) ----
        size_t i = ((size_t)(bx - 1088) * 256 + tid) * 16;
        const int b  = (int)(i >> 19);             // / (SS*EE)
        const int sr = (int)((i >> 9) & 1023);     // states row within batch
        if (sr >= lengths[b]) return;              // GEMM never reads beyond row len-1 (+1 window)
        #pragma unroll
        for (int q = 0; q < 2; ++q) {
            float4 v0 = *(const float4*)(states + i + q * 8);
            float4 v1 = *(const float4*)(states + i + q * 8 + 4);
            __nv_bfloat16 h[8];
            h[0] = __float2bfloat16(v0.x); h[1] = __float2bfloat16(v0.y);
            h[2] = __float2bfloat16(v0.z); h[3] = __float2bfloat16(v0.w);
            h[4] = __float2bfloat16(v1.x); h[5] = __float2bfloat16(v1.y);
            h[6] = __float2bfloat16(v1.z); h[7] = __float2bfloat16(v1.w);
            *(uint4*)(g_states_h + i + q * 8) = *(uint4*)h;
        }
    }
}

// ---------------------------------------------------------------------------
// Kernel A: scores = relu(X @ W1p + b1p) . w2p  via mma.sync bf16 (HMMA)
// PACKED tiles: tile t covers rowmap[t*128 .. t*128+127] (dense valid rows).
// 256 thr = 8 warps (4M x 2N), 2 CTAs/SM, 3-stage cp.async ring, dist-2.
// Mainloop order: sync -> h=0 MMA (tensor busy) -> fill(g+2) -> h=1..3 -> epi.
// (R13 configuration — measured best; M=256 variant was neutral/worse.)
// ---------------------------------------------------------------------------
#define TSTRIDE 72                    // halves: 144B row, 16B aligned, ldmatrix conflict-free
#define TILE_HALVES (128 * TSTRIDE)
#define TILE_BYTES  (TILE_HALVES * 2) // 18432
#define STAGE_BYTES (2 * TILE_BYTES)  // 36864 (A + B)
#define NSTAGE 3
#define RED_OFF     (NSTAGE * STAGE_BYTES) // 110592
#define MAP_OFF     (RED_OFF + 128 * 2 * 4)
#define DSM_TOTAL   (MAP_OFF + 128 * 4)

extern __shared__ char dsm[];

__global__ __launch_bounds__(256, 2) void pos_scores_mma(
    const float* __restrict__ b1p, const float* __restrict__ w2p)
{
    const int tid  = threadIdx.x;
    const int lane = tid & 31;
    const int w    = tid >> 5;
    const int mw   = w & 3;        // M warp 0..3 (32 rows each)
    const int nw   = w >> 2;       // N warp 0..1 (64 cols each)
    const int t    = blockIdx.x;

    const int L = g_nrows;
    if (t * 128 >= L) return;

    const uint32_t base = smem_u32(dsm);
    float* red = (float*)(dsm + RED_OFF);
    int*   smap = (int*)(dsm + MAP_OFF);

    if (tid < 128) smap[tid] = g_rowmap[t * 128 + tid];
    __syncthreads();

    // ldmatrix per-lane address components
    const int rA = (lane & 7) + 8 * ((lane >> 3) & 1);
    const int kA = 8 * (lane >> 4);
    const int rB = (lane & 7) + 8 * (lane >> 4);
    const int kB = 8 * ((lane >> 3) & 1);

    float acc[2][8][4];
    #pragma unroll
    for (int mt = 0; mt < 2; ++mt)
        #pragma unroll
        for (int nt = 0; nt < 8; ++nt)
            #pragma unroll
            for (int r = 0; r < 4; ++r) acc[mt][nt][r] = 0.f;
    float ps[2][2] = {{0.f, 0.f}, {0.f, 0.f}};

    // stage filler: gg -> nc = gg>>4 (N chunk), k0 = (gg&15)*64; buf explicit
    auto fill = [&](int gg, int buf) {
        const int n0  = (gg >> 4) << 7;
        const int k0  = (gg & 15) << 6;
        const uint32_t ab = base + buf * STAGE_BYTES;
        const uint32_t bb = ab + TILE_BYTES;
        #pragma unroll
        for (int i = 0; i < 4; ++i) {
            const int c = i * 256 + tid;         // 0..1023
            const int row = c >> 3, seg = c & 7;
            const uint32_t doff = (row * TSTRIDE + seg * 8) * 2;
            const int brow = smap[row];          // packed (b<<10)+s
            cp_async16(ab + doff, g_states_h + ((size_t)brow << 9) + k0 + seg * 8);
            cp_async16(bb + doff, g_W1pT + ((size_t)(n0 + row) << 10) + k0 + seg * 8);
        }
    };

    fill(0, 0); CP_COMMIT();
    fill(1, 1); CP_COMMIT();

    int buf = 0;        // stage holding iteration g
    int buf2 = 2;       // stage to fill with g+2

    for (int g = 0; g < 128; ++g) {
        const int nc  = g >> 4;
        const int kit = g & 15;

        if (g == 127) { CP_WAIT0(); } else { CP_WAIT1(); }
        __syncthreads();   // all warps past compute(g-1); buffer buf2 reusable

        const uint32_t ab = base + buf * STAGE_BYTES;
        const uint32_t bb = ab + TILE_BYTES;

        // ---- h = 0 first: get tensor pipe busy before issuing next fill ----
        {
            uint32_t af[2][4];
            #pragma unroll
            for (int mt = 0; mt < 2; ++mt)
                ldmx4(af[mt], ab + ((mw * 32 + mt * 16 + rA) * TSTRIDE + kA) * 2);
            uint32_t bf[4][4];
            #pragma unroll
            for (int bt = 0; bt < 4; ++bt)
                ldmx4(bf[bt], bb + ((nw * 64 + bt * 16 + rB) * TSTRIDE + kB) * 2);
            #pragma unroll
            for (int mt = 0; mt < 2; ++mt)
                #pragma unroll
                for (int nt = 0; nt < 8; ++nt)
                    mma16816(acc[mt][nt], af[mt], bf[nt >> 1][(nt & 1) * 2], bf[nt >> 1][(nt & 1) * 2 + 1]);
        }

        // ---- issue next stage while MMAs for h=0 drain ----
        if (g + 2 < 128) { fill(g + 2, buf2); CP_COMMIT(); }

        // ---- h = 1..3 ----
        #pragma unroll
        for (int h = 1; h < 4; ++h) {
            uint32_t af[2][4];
            #pragma unroll
            for (int mt = 0; mt < 2; ++mt)
                ldmx4(af[mt], ab + ((mw * 32 + mt * 16 + rA) * TSTRIDE + h * 16 + kA) * 2);
            uint32_t bf[4][4];
            #pragma unroll
            for (int bt = 0; bt < 4; ++bt)
                ldmx4(bf[bt], bb + ((nw * 64 + bt * 16 + rB) * TSTRIDE + h * 16 + kB) * 2);
            #pragma unroll
            for (int mt = 0; mt < 2; ++mt)
                #pragma unroll
                for (int nt = 0; nt < 8; ++nt)
                    mma16816(acc[mt][nt], af[mt], bf[nt >> 1][(nt & 1) * 2], bf[nt >> 1][(nt & 1) * 2 + 1]);
        }

        if (kit == 15) {
            // fused epilogue for this N-chunk: relu(acc + b1p) . w2p, row-reduce
            const int nbase = nc * 128 + nw * 64 + 2 * (lane & 3);
            #pragma unroll
            for (int mt = 0; mt < 2; ++mt) {
                float r0 = 0.f, r1 = 0.f;
                #pragma unroll
                for (int nt = 0; nt < 8; ++nt) {
                    const int n = nbase + nt * 8;
                    const float bb0 = __ldg(b1p + n),     ww0 = __ldg(w2p + n);
                    const float bb1 = __ldg(b1p + n + 1), ww1 = __ldg(w2p + n + 1);
                    r0 += fmaxf(acc[mt][nt][0] + bb0, 0.f) * ww0
                        + fmaxf(acc[mt][nt][1] + bb1, 0.f) * ww1;
                    r1 += fmaxf(acc[mt][nt][2] + bb0, 0.f) * ww0
                        + fmaxf(acc[mt][nt][3] + bb1, 0.f) * ww1;
                    acc[mt][nt][0] = acc[mt][nt][1] = acc[mt][nt][2] = acc[mt][nt][3] = 0.f;
                }
                r0 += __shfl_xor_sync(0xFFFFFFFFu, r0, 1);
                r0 += __shfl_xor_sync(0xFFFFFFFFu, r0, 2);
                r1 += __shfl_xor_sync(0xFFFFFFFFu, r1, 1);
                r1 += __shfl_xor_sync(0xFFFFFFFFu, r1, 2);
                ps[mt][0] += r0;
                ps[mt][1] += r1;
            }
        }

        const int nbuf = (buf == 2) ? 0 : buf + 1;
        buf2 = buf;
        buf = nbuf;
    }

    if ((lane & 3) == 0) {
        #pragma unroll
        for (int mt = 0; mt < 2; ++mt) {
            red[(mw * 32 + mt * 16 + (lane >> 2)) * 2 + nw]       = ps[mt][0];
            red[(mw * 32 + mt * 16 + (lane >> 2) + 8) * 2 + nw]   = ps[mt][1];
        }
    }
    __syncthreads();
    if (tid < 128 && t * 128 + tid < L) {
        g_scores[smap[tid]] = red[tid * 2] + red[tid * 2 + 1];   // smap value == b*SS + s
    }
}

// ---------------------------------------------------------------------------
// Kernel B: masked log-softmax over positions -> rows 0, 3
// ---------------------------------------------------------------------------
__global__ __launch_bounds__(256) void pos_softmax_kernel(
    const int* __restrict__ lengths, const int* __restrict__ pos_action,
    float* __restrict__ out)
{
    const int b = blockIdx.x;
    const int tid = threadIdx.x;
    const int len = lengths[b] - 1;
    const float* sc = g_scores + b * SS;

    __shared__ float r1[256], r2[256];

    float m = -FLT_MAX;
    for (int s = tid; s < len; s += 256) m = fmaxf(m, sc[s]);
    r1[tid] = m; __syncthreads();
    for (int off = 128; off > 0; off >>= 1) {
        if (tid < off) r1[tid] = fmaxf(r1[tid], r1[tid + off]);
        __syncthreads();
    }
    const float mx = r1[0];
    __syncthreads();

    float s1 = 0.f, s2 = 0.f;
    for (int s = tid; s < len; s += 256) {
        float v = sc[s];
        float e = expf(v - mx);
        s1 += e; s2 += e * v;
    }
    r1[tid] = s1; r2[tid] = s2; __syncthreads();
    for (int off = 128; off > 0; off >>= 1) {
        if (tid < off) { r1[tid] += r1[tid + off]; r2[tid] += r2[tid + off]; }
        __syncthreads();
    }
    if (tid == 0) {
        float lse = mx + logf(r1[0]);
        out[0 * BN + b] = sc[pos_action[b]] - lse;
        out[3 * BN + b] = lse - r2[0] / r1[0];
    }
}

// ---------------------------------------------------------------------------
// Kernel C1: sh = relu(X @ W1s + b1s), FOUR batches per block (W1s reuse)
// grid (16, 4), 256 threads
// ---------------------------------------------------------------------------
__global__ __launch_bounds__(256) void symbol_h_kernel(
    const float* __restrict__ states, const float* __restrict__ W1s,
    const float* __restrict__ b1s, const int* __restrict__ pos_action)
{
    const int bb = blockIdx.x * 4;
    const int f = blockIdx.y * 256 + threadIdx.x;
    const int tid = threadIdx.x;

    __shared__ float xs[4][KK];
    #pragma unroll
    for (int j = 0; j < 4; ++j) {
        const float* xp = states + (size_t)(bb + j) * SS * EE + (size_t)pos_action[bb + j] * EE;
        for (int i = tid; i < KK; i += 256) xs[j][i] = xp[i];
    }
    __syncthreads();

    const float bias = b1s[f];
    float a0 = bias, a1 = bias, a2 = bias, a3 = bias;
    for (int k = 0; k < KK; ++k) {
        const float wv = W1s[(size_t)k * KK + f];
        a0 = fmaf(xs[0][k], wv, a0);
        a1 = fmaf(xs[1][k], wv, a1);
        a2 = fmaf(xs[2][k], wv, a2);
        a3 = fmaf(xs[3][k], wv, a3);
    }
    g_sh[(bb + 0) * KK + f] = fmaxf(a0, 0.f);
    g_sh[(bb + 1) * KK + f] = fmaxf(a1, 0.f);
    g_sh[(bb + 2) * KK + f] = fmaxf(a2, 0.f);
    g_sh[(bb + 3) * KK + f] = fmaxf(a3, 0.f);
}

// ---------------------------------------------------------------------------
// Kernel C2: symbol logits + softmax -> rows 1, 4
// ---------------------------------------------------------------------------
__global__ __launch_bounds__(128) void symbol_logits_kernel(
    const float* __restrict__ W2s, const float* __restrict__ b2s,
    const int* __restrict__ sym_action, float* __restrict__ out)
{
    const int b = blockIdx.x;
    const int tid = threadIdx.x;

    __shared__ float sh[KK];
    __shared__ float lg[AA];
    __shared__ float r1[128], r2[128];

    for (int i = tid; i < KK; i += 128) sh[i] = g_sh[b * KK + i];
    __syncthreads();

    float s = b2s[tid];
    #pragma unroll 8
    for (int k = 0; k < KK; ++k) s = fmaf(sh[k], W2s[(size_t)k * AA + tid], s);
    lg[tid] = s;
    r1[tid] = s;
    __syncthreads();
    for (int off = 64; off > 0; off >>= 1) {
        if (tid < off) r1[tid] = fmaxf(r1[tid], r1[tid + off]);
        __syncthreads();
    }
    const float mx = r1[0];
    __syncthreads();
    float e = expf(lg[tid] - mx);
    r1[tid] = e; r2[tid] = e * lg[tid];
    __syncthreads();
    for (int off = 64; off > 0; off >>= 1) {
        if (tid < off) { r1[tid] += r1[tid + off]; r2[tid] += r2[tid + off]; }
        __syncthreads();
    }
    if (tid == 0) {
        float lse = mx + logf(r1[0]);
        out[1 * BN + b] = lg[sym_action[b]] - lse;
        out[4 * BN + b] = lse - r2[0] / r1[0];
    }
}

// ---------------------------------------------------------------------------
// Kernel D: value head -> row 2. grid 64 (1 batch/block), 256 threads, 2 f each.
// ---------------------------------------------------------------------------
__global__ __launch_bounds__(256) void value_kernel(
    const float* __restrict__ cls, const float* __restrict__ Wc1,
    const float* __restrict__ bc1, const float* __restrict__ wc2,
    const float* __restrict__ bc2, float* __restrict__ out)
{
    const int b = blockIdx.x;
    const int tid = threadIdx.x;

    __shared__ float xs[EE];
    __shared__ float r1[256];

    for (int i = tid; i < EE; i += 256) xs[i] = cls[(size_t)b * EE + i];
    __syncthreads();

    float a0 = bc1[tid], a1 = bc1[tid + 256];
    #pragma unroll 8
    for (int k = 0; k < EE; ++k) {
        const float xk = xs[k];
        const float* wr = Wc1 + (size_t)k * EE;
        a0 = fmaf(xk, wr[tid],       a0);
        a1 = fmaf(xk, wr[tid + 256], a1);
    }
    r1[tid] = fmaxf(a0, 0.f) * wc2[tid] + fmaxf(a1, 0.f) * wc2[tid + 256];
    __syncthreads();
    for (int off = 128; off > 0; off >>= 1) {
        if (tid < off) r1[tid] += r1[tid + off];
        __syncthreads();
    }
    if (tid == 0) out[2 * BN + b] = r1[0] + bc2[0];
}

// ---------------------------------------------------------------------------
extern "C" void kernel_launch(void* const* d_in, const int* in_sizes, int n_in,
                              void* d_out, int out_size)
{
    const float* states     = (const float*)d_in[0];
    const float* cls_token  = (const float*)d_in[1];
    const float* W1p        = (const float*)d_in[2];
    const float* b1p        = (const float*)d_in[3];
    const float* w2p        = (const float*)d_in[4];
    // d_in[5] = b2p : constant shift, cancels in log_softmax
    const float* W1s        = (const float*)d_in[6];
    const float* b1s        = (const float*)d_in[7];
    const float* W2s        = (const float*)d_in[8];
    const float* b2s        = (const float*)d_in[9];
    const float* Wc1        = (const float*)d_in[10];
    const float* bc1        = (const float*)d_in[11];
    const float* wc2        = (const float*)d_in[12];
    const float* bc2        = (const float*)d_in[13];
    const int*   lengths    = (const int*)d_in[14];
    const int*   pos_action = (const int*)d_in[15];
    const int*   sym_action = (const int*)d_in[16];
    float* out = (float*)d_out;

    static int configured = 0;
    static cudaStream_t s1, s2;
    static cudaEvent_t efork, ejoin1, ejoin2;
    if (!configured) {
        cudaFuncSetAttribute(pos_scores_mma, cudaFuncAttributeMaxDynamicSharedMemorySize, DSM_TOTAL);
        cudaStreamCreateWithFlags(&s1, cudaStreamNonBlocking);
        cudaStreamCreateWithFlags(&s2, cudaStreamNonBlocking);
        cudaEventCreateWithFlags(&efork,  cudaEventDisableTiming);
        cudaEventCreateWithFlags(&ejoin1, cudaEventDisableTiming);
        cudaEventCreateWithFlags(&ejoin2, cudaEventDisableTiming);
        configured = 1;
    }

    // main: DRAM-bound prep runs alone first (side branches would contend for HBM)
    prep_kernel<<<9280, 256>>>(states, W1p, lengths);

    // fork AFTER prep: side branches overlap the tensor-bound GEMM instead
    cudaEventRecord(efork, 0);
    cudaStreamWaitEvent(s1, efork, 0);
    cudaStreamWaitEvent(s2, efork, 0);

    // branch s1: symbol head (independent of GEMM chain)
    symbol_h_kernel<<<dim3(16, 4), 256, 0, s1>>>(states, W1s, b1s, pos_action);
    symbol_logits_kernel<<<BN, 128, 0, s1>>>(W2s, b2s, sym_action, out);
    cudaEventRecord(ejoin1, s1);

    // branch s2: value head
    value_kernel<<<BN, 256, 0, s2>>>(cls_token, Wc1, bc1, wc2, bc2, out);
    cudaEventRecord(ejoin2, s2);

    // main branch: GEMM + softmax
    pos_scores_mma<<<512, 256, DSM_TOTAL>>>(b1p, w2p);
    pos_softmax_kernel<<<BN, 256>>>(lengths, pos_action, out);

    // join
    cudaStreamWaitEvent(0, ejoin1, 0);
    cudaStreamWaitEvent(0, ejoin2, 0);
}

// round 16
// speedup vs baseline: 1.0176x; 1.0176x over previous
#include <cuda_runtime.h>
#include <cuda_bf16.h>
#include <cfloat>
#include <cmath>
#include <cstdint>

#define BN 64
#define SS 1024
#define EE 512
#define KK 1024
#define AA 128

// ------------------------- device scratch -------------------------
__device__ float g_scores[BN * SS];
__device__ float g_sh[BN * KK];
__device__ __align__(128) __nv_bfloat16 g_states_h[(size_t)BN * SS * EE + 1024]; // +pad for (b=63,s=1023) window
__device__ __align__(128) __nv_bfloat16 g_W1pT[(size_t)KK * KK];                 // [f][k]
__device__ int g_rowmap[BN * SS + 128];   // packed valid rows: value = b*1024 + s
__device__ int g_nrows;                   // number of valid rows L

// ------------------------- helpers -------------------------
__device__ __forceinline__ uint32_t smem_u32(const void* p) {
    uint32_t a;
    asm("{ .reg .u64 t; cvta.to.shared.u64 t, %1; cvt.u32.u64 %0, t; }" : "=r"(a) : "l"(p));
    return a;
}
__device__ __forceinline__ void cp_async16(uint32_t dst, const void* src) {
    asm volatile("cp.async.cg.shared.global [%0], [%1], 16;" :: "r"(dst), "l"(src) : "memory");
}
#define CP_COMMIT() asm volatile("cp.async.commit_group;" ::: "memory")
#define CP_WAIT1()  asm volatile("cp.async.wait_group 1;" ::: "memory")
#define CP_WAIT0()  asm volatile("cp.async.wait_group 0;" ::: "memory")

__device__ __forceinline__ void ldmx4(uint32_t* r, uint32_t addr) {
    asm volatile("ldmatrix.sync.aligned.m8n8.x4.shared.b16 {%0,%1,%2,%3}, [%4];"
        : "=r"(r[0]), "=r"(r[1]), "=r"(r[2]), "=r"(r[3]) : "r"(addr));
}
__device__ __forceinline__ void mma16816(float* c, const uint32_t* a, uint32_t b0, uint32_t b1) {
    asm volatile("mma.sync.aligned.m16n8k16.row.col.f32.bf16.bf16.f32 "
        "{%0,%1,%2,%3}, {%4,%5,%6,%7}, {%8,%9}, {%0,%1,%2,%3};"
        : "+f"(c[0]), "+f"(c[1]), "+f"(c[2]), "+f"(c[3])
        : "r"(a[0]), "r"(a[1]), "r"(a[2]), "r"(a[3]), "r"(b0), "r"(b1));
}

// ---------------------------------------------------------------------------
// Merged prep kernel (grid 9408):
//   [0,64)        symbol hidden: sh = relu(X @ W1s + b1s), 4 batches/block
//   [64,128)      value head -> out row 2
//   [128,192)     row map (pack valid (b,s))
//   [192,1216)    W1p transpose + bf16
//   [1216,9408)   states -> bf16 (valid rows only)
// Long-pole blocks (symbol/value) placed first so they start earliest.
// ---------------------------------------------------------------------------
__global__ __launch_bounds__(256) void prep_kernel(
    const float* __restrict__ states, const float* __restrict__ W1p,
    const int* __restrict__ lengths,
    const float* __restrict__ W1s, const float* __restrict__ b1s,
    const int* __restrict__ pos_action,
    const float* __restrict__ cls, const float* __restrict__ Wc1,
    const float* __restrict__ bc1, const float* __restrict__ wc2,
    const float* __restrict__ bc2, float* __restrict__ out)
{
    const int bx = blockIdx.x;
    const int tid = threadIdx.x;

    if (bx < 64) {
        // ---- symbol hidden: 4 batches per block (W1s reuse), f-chunk of 256 ----
        __shared__ float xs[4][KK];
        const int r = bx;
        const int bb = (r & 15) * 4;
        const int f = (r >> 4) * 256 + tid;
        #pragma unroll
        for (int j = 0; j < 4; ++j) {
            const float* xp = states + (size_t)(bb + j) * SS * EE + (size_t)pos_action[bb + j] * EE;
            for (int i = tid; i < KK; i += 256) xs[j][i] = xp[i];
        }
        __syncthreads();
        const float bias = b1s[f];
        float a0 = bias, a1 = bias, a2 = bias, a3 = bias;
        for (int k = 0; k < KK; ++k) {
            const float wv = W1s[(size_t)k * KK + f];
            a0 = fmaf(xs[0][k], wv, a0);
            a1 = fmaf(xs[1][k], wv, a1);
            a2 = fmaf(xs[2][k], wv, a2);
            a3 = fmaf(xs[3][k], wv, a3);
        }
        g_sh[(bb + 0) * KK + f] = fmaxf(a0, 0.f);
        g_sh[(bb + 1) * KK + f] = fmaxf(a1, 0.f);
        g_sh[(bb + 2) * KK + f] = fmaxf(a2, 0.f);
        g_sh[(bb + 3) * KK + f] = fmaxf(a3, 0.f);
    } else if (bx < 128) {
        // ---- value head ----
        __shared__ float xv[EE];
        __shared__ float rv[256];
        const int b = bx - 64;
        for (int i = tid; i < EE; i += 256) xv[i] = cls[(size_t)b * EE + i];
        __syncthreads();
        float a0 = bc1[tid], a1 = bc1[tid + 256];
        #pragma unroll 8
        for (int k = 0; k < EE; ++k) {
            const float xk = xv[k];
            const float* wr = Wc1 + (size_t)k * EE;
            a0 = fmaf(xk, wr[tid],       a0);
            a1 = fmaf(xk, wr[tid + 256], a1);
        }
        rv[tid] = fmaxf(a0, 0.f) * wc2[tid] + fmaxf(a1, 0.f) * wc2[tid + 256];
        __syncthreads();
        for (int off = 128; off > 0; off >>= 1) {
            if (tid < off) rv[tid] += rv[tid + off];
            __syncthreads();
        }
        if (tid == 0) out[2 * BN + b] = rv[0] + bc2[0];
    } else if (bx < 192) {
        // ---- row map ----
        __shared__ int pref[65];
        const int b = bx - 128;
        if (tid == 0) {
            int a = 0; pref[0] = 0;
            for (int i = 0; i < 64; ++i) { a += lengths[i] - 1; pref[i + 1] = a; }
            if (b == 0) g_nrows = a;
        }
        __syncthreads();
        const int p = pref[b], n = pref[b + 1] - p, base = b << 10;
        for (int j = tid; j < n; j += 256) g_rowmap[p + j] = base + j;
        if (b == 63) {
            const int L = pref[64];
            const int Lpad = (L + 127) & ~127;
            for (int j = L + tid; j < Lpad; j += 256) g_rowmap[j] = 0;  // padded rows -> safe row 0
        }
    } else if (bx < 1216) {
        // ---- W1p transpose + bf16 ----
        __shared__ __nv_bfloat16 t[32][33];
        const int c = bx - 192;
        const int txb = c & 31, tyb = c >> 5;     // 32 x 32 tile grid
        const int tx = tid & 31, ty = tid >> 5;   // 32 x 8 threads
        #pragma unroll
        for (int i = 0; i < 4; ++i)
            t[ty + i * 8][tx] = __float2bfloat16(W1p[(size_t)(tyb * 32 + ty + i * 8) * KK + txb * 32 + tx]);
        __syncthreads();
        #pragma unroll
        for (int i = 0; i < 4; ++i)
            g_W1pT[(size_t)(txb * 32 + ty + i * 8) * KK + tyb * 32 + tx] = t[tx][ty + i * 8];
    } else {
        // ---- states -> bf16 (valid rows only) ----
        size_t i = ((size_t)(bx - 1216) * 256 + tid) * 16;
        const int b  = (int)(i >> 19);             // / (SS*EE)
        const int sr = (int)((i >> 9) & 1023);     // states row within batch
        if (sr >= lengths[b]) return;              // GEMM never reads beyond row len-1 (+1 window)
        #pragma unroll
        for (int q = 0; q < 2; ++q) {
            float4 v0 = *(const float4*)(states + i + q * 8);
            float4 v1 = *(const float4*)(states + i + q * 8 + 4);
            __nv_bfloat16 h[8];
            h[0] = __float2bfloat16(v0.x); h[1] = __float2bfloat16(v0.y);
            h[2] = __float2bfloat16(v0.z); h[3] = __float2bfloat16(v0.w);
            h[4] = __float2bfloat16(v1.x); h[5] = __float2bfloat16(v1.y);
            h[6] = __float2bfloat16(v1.z); h[7] = __float2bfloat16(v1.w);
            *(uint4*)(g_states_h + i + q * 8) = *(uint4*)h;
        }
    }
}

// ---------------------------------------------------------------------------
// Kernel A: scores = relu(X @ W1p + b1p) . w2p  via mma.sync bf16 (HMMA)
// PACKED tiles: tile t covers rowmap[t*128 .. t*128+127] (dense valid rows).
// 256 thr = 8 warps (4M x 2N), 2 CTAs/SM, 3-stage cp.async ring, dist-2.
// Mainloop order: sync -> h=0 MMA (tensor busy) -> fill(g+2) -> h=1..3 -> epi.
// ---------------------------------------------------------------------------
#define TSTRIDE 72                    // halves: 144B row, 16B aligned, ldmatrix conflict-free
#define TILE_HALVES (128 * TSTRIDE)
#define TILE_BYTES  (TILE_HALVES * 2) // 18432
#define STAGE_BYTES (2 * TILE_BYTES)  // 36864 (A + B)
#define NSTAGE 3
#define RED_OFF     (NSTAGE * STAGE_BYTES) // 110592
#define MAP_OFF     (RED_OFF + 128 * 2 * 4)
#define DSM_TOTAL   (MAP_OFF + 128 * 4)

extern __shared__ char dsm[];

__global__ __launch_bounds__(256, 2) void pos_scores_mma(
    const float* __restrict__ b1p, const float* __restrict__ w2p)
{
    const int tid  = threadIdx.x;
    const int lane = tid & 31;
    const int w    = tid >> 5;
    const int mw   = w & 3;        // M warp 0..3 (32 rows each)
    const int nw   = w >> 2;       // N warp 0..1 (64 cols each)
    const int t    = blockIdx.x;

    const int L = g_nrows;
    if (t * 128 >= L) return;

    const uint32_t base = smem_u32(dsm);
    float* red = (float*)(dsm + RED_OFF);
    int*   smap = (int*)(dsm + MAP_OFF);

    if (tid < 128) smap[tid] = g_rowmap[t * 128 + tid];
    __syncthreads();

    // ldmatrix per-lane address components
    const int rA = (lane & 7) + 8 * ((lane >> 3) & 1);
    const int kA = 8 * (lane >> 4);
    const int rB = (lane & 7) + 8 * (lane >> 4);
    const int kB = 8 * ((lane >> 3) & 1);

    float acc[2][8][4];
    #pragma unroll
    for (int mt = 0; mt < 2; ++mt)
        #pragma unroll
        for (int nt = 0; nt < 8; ++nt)
            #pragma unroll
            for (int r = 0; r < 4; ++r) acc[mt][nt][r] = 0.f;
    float ps[2][2] = {{0.f, 0.f}, {0.f, 0.f}};

    // stage filler: gg -> nc = gg>>4 (N chunk), k0 = (gg&15)*64; buf explicit
    auto fill = [&](int gg, int buf) {
        const int n0  = (gg >> 4) << 7;
        const int k0  = (gg & 15) << 6;
        const uint32_t ab = base + buf * STAGE_BYTES;
        const uint32_t bb = ab + TILE_BYTES;
        #pragma unroll
        for (int i = 0; i < 4; ++i) {
            const int c = i * 256 + tid;         // 0..1023
            const int row = c >> 3, seg = c & 7;
            const uint32_t doff = (row * TSTRIDE + seg * 8) * 2;
            const int brow = smap[row];          // packed (b<<10)+s
            cp_async16(ab + doff, g_states_h + ((size_t)brow << 9) + k0 + seg * 8);
            cp_async16(bb + doff, g_W1pT + ((size_t)(n0 + row) << 10) + k0 + seg * 8);
        }
    };

    fill(0, 0); CP_COMMIT();
    fill(1, 1); CP_COMMIT();

    int buf = 0;        // stage holding iteration g
    int buf2 = 2;       // stage to fill with g+2

    for (int g = 0; g < 128; ++g) {
        const int nc  = g >> 4;
        const int kit = g & 15;

        if (g == 127) { CP_WAIT0(); } else { CP_WAIT1(); }
        __syncthreads();   // all warps past compute(g-1); buffer buf2 reusable

        const uint32_t ab = base + buf * STAGE_BYTES;
        const uint32_t bb = ab + TILE_BYTES;

        // ---- h = 0 first: get tensor pipe busy before issuing next fill ----
        {
            uint32_t af[2][4];
            #pragma unroll
            for (int mt = 0; mt < 2; ++mt)
                ldmx4(af[mt], ab + ((mw * 32 + mt * 16 + rA) * TSTRIDE + kA) * 2);
            uint32_t bf[4][4];
            #pragma unroll
            for (int bt = 0; bt < 4; ++bt)
                ldmx4(bf[bt], bb + ((nw * 64 + bt * 16 + rB) * TSTRIDE + kB) * 2);
            #pragma unroll
            for (int mt = 0; mt < 2; ++mt)
                #pragma unroll
                for (int nt = 0; nt < 8; ++nt)
                    mma16816(acc[mt][nt], af[mt], bf[nt >> 1][(nt & 1) * 2], bf[nt >> 1][(nt & 1) * 2 + 1]);
        }

        // ---- issue next stage while MMAs for h=0 drain ----
        if (g + 2 < 128) { fill(g + 2, buf2); CP_COMMIT(); }

        // ---- h = 1..3 ----
        #pragma unroll
        for (int h = 1; h < 4; ++h) {
            uint32_t af[2][4];
            #pragma unroll
            for (int mt = 0; mt < 2; ++mt)
                ldmx4(af[mt], ab + ((mw * 32 + mt * 16 + rA) * TSTRIDE + h * 16 + kA) * 2);
            uint32_t bf[4][4];
            #pragma unroll
            for (int bt = 0; bt < 4; ++bt)
                ldmx4(bf[bt], bb + ((nw * 64 + bt * 16 + rB) * TSTRIDE + h * 16 + kB) * 2);
            #pragma unroll
            for (int mt = 0; mt < 2; ++mt)
                #pragma unroll
                for (int nt = 0; nt < 8; ++nt)
                    mma16816(acc[mt][nt], af[mt], bf[nt >> 1][(nt & 1) * 2], bf[nt >> 1][(nt & 1) * 2 + 1]);
        }

        if (kit == 15) {
            // fused epilogue for this N-chunk: relu(acc + b1p) . w2p, row-reduce
            const int nbase = nc * 128 + nw * 64 + 2 * (lane & 3);
            #pragma unroll
            for (int mt = 0; mt < 2; ++mt) {
                float r0 = 0.f, r1 = 0.f;
                #pragma unroll
                for (int nt = 0; nt < 8; ++nt) {
                    const int n = nbase + nt * 8;
                    const float bb0 = __ldg(b1p + n),     ww0 = __ldg(w2p + n);
                    const float bb1 = __ldg(b1p + n + 1), ww1 = __ldg(w2p + n + 1);
                    r0 += fmaxf(acc[mt][nt][0] + bb0, 0.f) * ww0
                        + fmaxf(acc[mt][nt][1] + bb1, 0.f) * ww1;
                    r1 += fmaxf(acc[mt][nt][2] + bb0, 0.f) * ww0
                        + fmaxf(acc[mt][nt][3] + bb1, 0.f) * ww1;
                    acc[mt][nt][0] = acc[mt][nt][1] = acc[mt][nt][2] = acc[mt][nt][3] = 0.f;
                }
                r0 += __shfl_xor_sync(0xFFFFFFFFu, r0, 1);
                r0 += __shfl_xor_sync(0xFFFFFFFFu, r0, 2);
                r1 += __shfl_xor_sync(0xFFFFFFFFu, r1, 1);
                r1 += __shfl_xor_sync(0xFFFFFFFFu, r1, 2);
                ps[mt][0] += r0;
                ps[mt][1] += r1;
            }
        }

        const int nbuf = (buf == 2) ? 0 : buf + 1;
        buf2 = buf;
        buf = nbuf;
    }

    if ((lane & 3) == 0) {
        #pragma unroll
        for (int mt = 0; mt < 2; ++mt) {
            red[(mw * 32 + mt * 16 + (lane >> 2)) * 2 + nw]       = ps[mt][0];
            red[(mw * 32 + mt * 16 + (lane >> 2) + 8) * 2 + nw]   = ps[mt][1];
        }
    }
    __syncthreads();
    if (tid < 128 && t * 128 + tid < L) {
        g_scores[smap[tid]] = red[tid * 2] + red[tid * 2 + 1];   // smap value == b*SS + s
    }
}

// ---------------------------------------------------------------------------
// Kernel B: masked log-softmax over positions -> rows 0, 3
// ---------------------------------------------------------------------------
__global__ __launch_bounds__(256) void pos_softmax_kernel(
    const int* __restrict__ lengths, const int* __restrict__ pos_action,
    float* __restrict__ out)
{
    const int b = blockIdx.x;
    const int tid = threadIdx.x;
    const int len = lengths[b] - 1;
    const float* sc = g_scores + b * SS;

    __shared__ float r1[256], r2[256];

    float m = -FLT_MAX;
    for (int s = tid; s < len; s += 256) m = fmaxf(m, sc[s]);
    r1[tid] = m; __syncthreads();
    for (int off = 128; off > 0; off >>= 1) {
        if (tid < off) r1[tid] = fmaxf(r1[tid], r1[tid + off]);
        __syncthreads();
    }
    const float mx = r1[0];
    __syncthreads();

    float s1 = 0.f, s2 = 0.f;
    for (int s = tid; s < len; s += 256) {
        float v = sc[s];
        float e = expf(v - mx);
        s1 += e; s2 += e * v;
    }
    r1[tid] = s1; r2[tid] = s2; __syncthreads();
    for (int off = 128; off > 0; off >>= 1) {
        if (tid < off) { r1[tid] += r1[tid + off]; r2[tid] += r2[tid + off]; }
        __syncthreads();
    }
    if (tid == 0) {
        float lse = mx + logf(r1[0]);
        out[0 * BN + b] = sc[pos_action[b]] - lse;
        out[3 * BN + b] = lse - r2[0] / r1[0];
    }
}

// ---------------------------------------------------------------------------
// Kernel C2: symbol logits + softmax -> rows 1, 4
// ---------------------------------------------------------------------------
__global__ __launch_bounds__(128) void symbol_logits_kernel(
    const float* __restrict__ W2s, const float* __restrict__ b2s,
    const int* __restrict__ sym_action, float* __restrict__ out)
{
    const int b = blockIdx.x;
    const int tid = threadIdx.x;

    __shared__ float sh[KK];
    __shared__ float lg[AA];
    __shared__ float r1[128], r2[128];

    for (int i = tid; i < KK; i += 128) sh[i] = g_sh[b * KK + i];
    __syncthreads();

    float s = b2s[tid];
    #pragma unroll 8
    for (int k = 0; k < KK; ++k) s = fmaf(sh[k], W2s[(size_t)k * AA + tid], s);
    lg[tid] = s;
    r1[tid] = s;
    __syncthreads();
    for (int off = 64; off > 0; off >>= 1) {
        if (tid < off) r1[tid] = fmaxf(r1[tid], r1[tid + off]);
        __syncthreads();
    }
    const float mx = r1[0];
    __syncthreads();
    float e = expf(lg[tid] - mx);
    r1[tid] = e; r2[tid] = e * lg[tid];
    __syncthreads();
    for (int off = 64; off > 0; off >>= 1) {
        if (tid < off) { r1[tid] += r1[tid + off]; r2[tid] += r2[tid + off]; }
        __syncthreads();
    }
    if (tid == 0) {
        float lse = mx + logf(r1[0]);
        out[1 * BN + b] = lg[sym_action[b]] - lse;
        out[4 * BN + b] = lse - r2[0] / r1[0];
    }
}

// ---------------------------------------------------------------------------
extern "C" void kernel_launch(void* const* d_in, const int* in_sizes, int n_in,
                              void* d_out, int out_size)
{
    const float* states     = (const float*)d_in[0];
    const float* cls_token  = (const float*)d_in[1];
    const float* W1p        = (const float*)d_in[2];
    const float* b1p        = (const float*)d_in[3];
    const float* w2p        = (const float*)d_in[4];
    // d_in[5] = b2p : constant shift, cancels in log_softmax
    const float* W1s        = (const float*)d_in[6];
    const float* b1s        = (const float*)d_in[7];
    const float* W2s        = (const float*)d_in[8];
    const float* b2s        = (const float*)d_in[9];
    const float* Wc1        = (const float*)d_in[10];
    const float* bc1        = (const float*)d_in[11];
    const float* wc2        = (const float*)d_in[12];
    const float* bc2        = (const float*)d_in[13];
    const int*   lengths    = (const int*)d_in[14];
    const int*   pos_action = (const int*)d_in[15];
    const int*   sym_action = (const int*)d_in[16];
    float* out = (float*)d_out;

    static int configured = 0;
    static cudaStream_t s1;
    static cudaEvent_t eprep, ejoin1;
    if (!configured) {
        cudaFuncSetAttribute(pos_scores_mma, cudaFuncAttributeMaxDynamicSharedMemorySize, DSM_TOTAL);
        cudaStreamCreateWithFlags(&s1, cudaStreamNonBlocking);
        cudaEventCreateWithFlags(&eprep,  cudaEventDisableTiming);
        cudaEventCreateWithFlags(&ejoin1, cudaEventDisableTiming);
        configured = 1;
    }

    // merged prep: side heads (symbol_h, value) + rowmap + W1pT + states->bf16
    prep_kernel<<<9408, 256>>>(states, W1p, lengths, W1s, b1s, pos_action,
                               cls_token, Wc1, bc1, wc2, bc2, out);
    cudaEventRecord(eprep, 0);

    // side stream: symbol logits (needs g_sh from prep); overlaps the GEMM
    cudaStreamWaitEvent(s1, eprep, 0);
    symbol_logits_kernel<<<BN, 128, 0, s1>>>(W2s, b2s, sym_action, out);
    cudaEventRecord(ejoin1, s1);

    // main: GEMM + softmax
    pos_scores_mma<<<512, 256, DSM_TOTAL>>>(b1p, w2p);
    pos_softmax_kernel<<<BN, 256>>>(lengths, pos_action, out);

    // join
    cudaStreamWaitEvent(0, ejoin1, 0);
}

// round 17
// speedup vs baseline: 1.1974x; 1.1767x over previous
#include <cuda_runtime.h>
#include <cuda_bf16.h>
#include <cfloat>
#include <cmath>
#include <cstdint>

#define BN 64
#define SS 1024
#define EE 512
#define KK 1024
#define AA 128

// ------------------------- device scratch -------------------------
__device__ float g_scores[BN * SS];
__device__ float g_sh[BN * KK];
__device__ __align__(128) __nv_bfloat16 g_states_h[(size_t)BN * SS * EE + 1024]; // +pad for (b=63,s=1023) window
__device__ __align__(128) __nv_bfloat16 g_W1pT[(size_t)KK * KK];                 // [f][k]
__device__ int g_rowmap[BN * SS + 128];   // packed valid rows: value = b*1024 + s
__device__ int g_nrows;                   // number of valid rows L

// ------------------------- helpers -------------------------
__device__ __forceinline__ uint32_t smem_u32(const void* p) {
    uint32_t a;
    asm("{ .reg .u64 t; cvta.to.shared.u64 t, %1; cvt.u32.u64 %0, t; }" : "=r"(a) : "l"(p));
    return a;
}
__device__ __forceinline__ void cp_async16(uint32_t dst, const void* src) {
    asm volatile("cp.async.cg.shared.global [%0], [%1], 16;" :: "r"(dst), "l"(src) : "memory");
}
#define CP_COMMIT() asm volatile("cp.async.commit_group;" ::: "memory")
#define CP_WAIT1()  asm volatile("cp.async.wait_group 1;" ::: "memory")
#define CP_WAIT0()  asm volatile("cp.async.wait_group 0;" ::: "memory")

__device__ __forceinline__ void ldmx4(uint32_t* r, uint32_t addr) {
    asm volatile("ldmatrix.sync.aligned.m8n8.x4.shared.b16 {%0,%1,%2,%3}, [%4];"
        : "=r"(r[0]), "=r"(r[1]), "=r"(r[2]), "=r"(r[3]) : "r"(addr));
}
__device__ __forceinline__ void mma16816(float* c, const uint32_t* a, uint32_t b0, uint32_t b1) {
    asm volatile("mma.sync.aligned.m16n8k16.row.col.f32.bf16.bf16.f32 "
        "{%0,%1,%2,%3}, {%4,%5,%6,%7}, {%8,%9}, {%0,%1,%2,%3};"
        : "+f"(c[0]), "+f"(c[1]), "+f"(c[2]), "+f"(c[3])
        : "r"(a[0]), "r"(a[1]), "r"(a[2]), "r"(a[3]), "r"(b0), "r"(b1));
}

// ---------------------------------------------------------------------------
// Merged prep kernel: blocks [0,64) rowmap | [64,1088) W1p transpose+bf16 |
// [1088, 9280) states->bf16. Each block takes exactly one branch (uniform).
// ---------------------------------------------------------------------------
__global__ __launch_bounds__(256) void prep_kernel(
    const float* __restrict__ states, const float* __restrict__ W1p,
    const int* __restrict__ lengths)
{
    const int bx = blockIdx.x;
    const int tid = threadIdx.x;

    if (bx < 64) {
        // ---- row map ----
        __shared__ int pref[65];
        const int b = bx;
        if (tid == 0) {
            int a = 0; pref[0] = 0;
            for (int i = 0; i < 64; ++i) { a += lengths[i] - 1; pref[i + 1] = a; }
            if (b == 0) g_nrows = a;
        }
        __syncthreads();
        const int p = pref[b], n = pref[b + 1] - p, base = b << 10;
        for (int j = tid; j < n; j += 256) g_rowmap[p + j] = base + j;
        if (b == 63) {
            const int L = pref[64];
            const int Lpad = (L + 127) & ~127;
            for (int j = L + tid; j < Lpad; j += 256) g_rowmap[j] = 0;  // padded rows -> safe row 0
        }
    } else if (bx < 1088) {
        // ---- W1p transpose + bf16 ----
        __shared__ __nv_bfloat16 t[32][33];
        const int c = bx - 64;
        const int txb = c & 31, tyb = c >> 5;     // 32 x 32 tile grid
        const int tx = tid & 31, ty = tid >> 5;   // 32 x 8 threads
        #pragma unroll
        for (int i = 0; i < 4; ++i)
            t[ty + i * 8][tx] = __float2bfloat16(W1p[(size_t)(tyb * 32 + ty + i * 8) * KK + txb * 32 + tx]);
        __syncthreads();
        #pragma unroll
        for (int i = 0; i < 4; ++i)
            g_W1pT[(size_t)(txb * 32 + ty + i * 8) * KK + tyb * 32 + tx] = t[tx][ty + i * 8];
    } else {
        // ---- states -> bf16 (valid rows only) ----
        size_t i = ((size_t)(bx - 1088) * 256 + tid) * 16;
        const int b  = (int)(i >> 19);             // / (SS*EE)
        const int sr = (int)((i >> 9) & 1023);     // states row within batch
        if (sr >= lengths[b]) return;              // GEMM never reads beyond row len-1 (+1 window)
        #pragma unroll
        for (int q = 0; q < 2; ++q) {
            float4 v0 = *(const float4*)(states + i + q * 8);
            float4 v1 = *(const float4*)(states + i + q * 8 + 4);
            __nv_bfloat16 h[8];
            h[0] = __float2bfloat16(v0.x); h[1] = __float2bfloat16(v0.y);
            h[2] = __float2bfloat16(v0.z); h[3] = __float2bfloat16(v0.w);
            h[4] = __float2bfloat16(v1.x); h[5] = __float2bfloat16(v1.y);
            h[6] = __float2bfloat16(v1.z); h[7] = __float2bfloat16(v1.w);
            *(uint4*)(g_states_h + i + q * 8) = *(uint4*)h;
        }
    }
}

// ---------------------------------------------------------------------------
// Kernel A: scores = relu(X @ W1p + b1p) . w2p  via mma.sync bf16 (HMMA)
// PACKED tiles: tile t covers rowmap[t*128 .. t*128+127] (dense valid rows).
// 256 thr = 8 warps (4M x 2N), 2 CTAs/SM, 3-stage cp.async ring, dist-2.
// Mainloop order: sync -> h=0 MMA (tensor busy) -> fill(g+2) -> h=1..3 -> epi.
// ---------------------------------------------------------------------------
#define TSTRIDE 72                    // halves: 144B row, 16B aligned, ldmatrix conflict-free
#define TILE_HALVES (128 * TSTRIDE)
#define TILE_BYTES  (TILE_HALVES * 2) // 18432
#define STAGE_BYTES (2 * TILE_BYTES)  // 36864 (A + B)
#define NSTAGE 3
#define RED_OFF     (NSTAGE * STAGE_BYTES) // 110592
#define MAP_OFF     (RED_OFF + 128 * 2 * 4)
#define DSM_TOTAL   (MAP_OFF + 128 * 4)

extern __shared__ char dsm[];

__global__ __launch_bounds__(256, 2) void pos_scores_mma(
    const float* __restrict__ b1p, const float* __restrict__ w2p)
{
    const int tid  = threadIdx.x;
    const int lane = tid & 31;
    const int w    = tid >> 5;
    const int mw   = w & 3;        // M warp 0..3 (32 rows each)
    const int nw   = w >> 2;       // N warp 0..1 (64 cols each)
    const int t    = blockIdx.x;

    const int L = g_nrows;
    if (t * 128 >= L) return;

    const uint32_t base = smem_u32(dsm);
    float* red = (float*)(dsm + RED_OFF);
    int*   smap = (int*)(dsm + MAP_OFF);

    if (tid < 128) smap[tid] = g_rowmap[t * 128 + tid];
    __syncthreads();

    // ldmatrix per-lane address components
    const int rA = (lane & 7) + 8 * ((lane >> 3) & 1);
    const int kA = 8 * (lane >> 4);
    const int rB = (lane & 7) + 8 * (lane >> 4);
    const int kB = 8 * ((lane >> 3) & 1);

    float acc[2][8][4];
    #pragma unroll
    for (int mt = 0; mt < 2; ++mt)
        #pragma unroll
        for (int nt = 0; nt < 8; ++nt)
            #pragma unroll
            for (int r = 0; r < 4; ++r) acc[mt][nt][r] = 0.f;
    float ps[2][2] = {{0.f, 0.f}, {0.f, 0.f}};

    // stage filler: gg -> nc = gg>>4 (N chunk), k0 = (gg&15)*64; buf explicit
    auto fill = [&](int gg, int buf) {
        const int n0  = (gg >> 4) << 7;
        const int k0  = (gg & 15) << 6;
        const uint32_t ab = base + buf * STAGE_BYTES;
        const uint32_t bb = ab + TILE_BYTES;
        #pragma unroll
        for (int i = 0; i < 4; ++i) {
            const int c = i * 256 + tid;         // 0..1023
            const int row = c >> 3, seg = c & 7;
            const uint32_t doff = (row * TSTRIDE + seg * 8) * 2;
            const int brow = smap[row];          // packed (b<<10)+s
            cp_async16(ab + doff, g_states_h + ((size_t)brow << 9) + k0 + seg * 8);
            cp_async16(bb + doff, g_W1pT + ((size_t)(n0 + row) << 10) + k0 + seg * 8);
        }
    };

    fill(0, 0); CP_COMMIT();
    fill(1, 1); CP_COMMIT();

    int buf = 0;        // stage holding iteration g
    int buf2 = 2;       // stage to fill with g+2

    for (int g = 0; g < 128; ++g) {
        const int nc  = g >> 4;
        const int kit = g & 15;

        if (g == 127) { CP_WAIT0(); } else { CP_WAIT1(); }
        __syncthreads();   // all warps past compute(g-1); buffer buf2 reusable

        const uint32_t ab = base + buf * STAGE_BYTES;
        const uint32_t bb = ab + TILE_BYTES;

        // ---- h = 0 first: get tensor pipe busy before issuing next fill ----
        {
            uint32_t af[2][4];
            #pragma unroll
            for (int mt = 0; mt < 2; ++mt)
                ldmx4(af[mt], ab + ((mw * 32 + mt * 16 + rA) * TSTRIDE + kA) * 2);
            uint32_t bf[4][4];
            #pragma unroll
            for (int bt = 0; bt < 4; ++bt)
                ldmx4(bf[bt], bb + ((nw * 64 + bt * 16 + rB) * TSTRIDE + kB) * 2);
            #pragma unroll
            for (int mt = 0; mt < 2; ++mt)
                #pragma unroll
                for (int nt = 0; nt < 8; ++nt)
                    mma16816(acc[mt][nt], af[mt], bf[nt >> 1][(nt & 1) * 2], bf[nt >> 1][(nt & 1) * 2 + 1]);
        }

        // ---- issue next stage while MMAs for h=0 drain ----
        if (g + 2 < 128) { fill(g + 2, buf2); CP_COMMIT(); }

        // ---- h = 1..3 ----
        #pragma unroll
        for (int h = 1; h < 4; ++h) {
            uint32_t af[2][4];
            #pragma unroll
            for (int mt = 0; mt < 2; ++mt)
                ldmx4(af[mt], ab + ((mw * 32 + mt * 16 + rA) * TSTRIDE + h * 16 + kA) * 2);
            uint32_t bf[4][4];
            #pragma unroll
            for (int bt = 0; bt < 4; ++bt)
                ldmx4(bf[bt], bb + ((nw * 64 + bt * 16 + rB) * TSTRIDE + h * 16 + kB) * 2);
            #pragma unroll
            for (int mt = 0; mt < 2; ++mt)
                #pragma unroll
                for (int nt = 0; nt < 8; ++nt)
                    mma16816(acc[mt][nt], af[mt], bf[nt >> 1][(nt & 1) * 2], bf[nt >> 1][(nt & 1) * 2 + 1]);
        }

        if (kit == 15) {
            // fused epilogue for this N-chunk: relu(acc + b1p) . w2p, row-reduce
            const int nbase = nc * 128 + nw * 64 + 2 * (lane & 3);
            #pragma unroll
            for (int mt = 0; mt < 2; ++mt) {
                float r0 = 0.f, r1 = 0.f;
                #pragma unroll
                for (int nt = 0; nt < 8; ++nt) {
                    const int n = nbase + nt * 8;
                    const float bb0 = __ldg(b1p + n),     ww0 = __ldg(w2p + n);
                    const float bb1 = __ldg(b1p + n + 1), ww1 = __ldg(w2p + n + 1);
                    r0 += fmaxf(acc[mt][nt][0] + bb0, 0.f) * ww0
                        + fmaxf(acc[mt][nt][1] + bb1, 0.f) * ww1;
                    r1 += fmaxf(acc[mt][nt][2] + bb0, 0.f) * ww0
                        + fmaxf(acc[mt][nt][3] + bb1, 0.f) * ww1;
                    acc[mt][nt][0] = acc[mt][nt][1] = acc[mt][nt][2] = acc[mt][nt][3] = 0.f;
                }
                r0 += __shfl_xor_sync(0xFFFFFFFFu, r0, 1);
                r0 += __shfl_xor_sync(0xFFFFFFFFu, r0, 2);
                r1 += __shfl_xor_sync(0xFFFFFFFFu, r1, 1);
                r1 += __shfl_xor_sync(0xFFFFFFFFu, r1, 2);
                ps[mt][0] += r0;
                ps[mt][1] += r1;
            }
        }

        const int nbuf = (buf == 2) ? 0 : buf + 1;
        buf2 = buf;
        buf = nbuf;
    }

    if ((lane & 3) == 0) {
        #pragma unroll
        for (int mt = 0; mt < 2; ++mt) {
            red[(mw * 32 + mt * 16 + (lane >> 2)) * 2 + nw]       = ps[mt][0];
            red[(mw * 32 + mt * 16 + (lane >> 2) + 8) * 2 + nw]   = ps[mt][1];
        }
    }
    __syncthreads();
    if (tid < 128 && t * 128 + tid < L) {
        g_scores[smap[tid]] = red[tid * 2] + red[tid * 2 + 1];   // smap value == b*SS + s
    }
}

// ---------------------------------------------------------------------------
// Kernel B: masked log-softmax over positions -> rows 0, 3
// ---------------------------------------------------------------------------
__global__ __launch_bounds__(256) void pos_softmax_kernel(
    const int* __restrict__ lengths, const int* __restrict__ pos_action,
    float* __restrict__ out)
{
    const int b = blockIdx.x;
    const int tid = threadIdx.x;
    const int len = lengths[b] - 1;
    const float* sc = g_scores + b * SS;

    __shared__ float r1[256], r2[256];

    float m = -FLT_MAX;
    for (int s = tid; s < len; s += 256) m = fmaxf(m, sc[s]);
    r1[tid] = m; __syncthreads();
    for (int off = 128; off > 0; off >>= 1) {
        if (tid < off) r1[tid] = fmaxf(r1[tid], r1[tid + off]);
        __syncthreads();
    }
    const float mx = r1[0];
    __syncthreads();

    float s1 = 0.f, s2 = 0.f;
    for (int s = tid; s < len; s += 256) {
        float v = sc[s];
        float e = expf(v - mx);
        s1 += e; s2 += e * v;
    }
    r1[tid] = s1; r2[tid] = s2; __syncthreads();
    for (int off = 128; off > 0; off >>= 1) {
        if (tid < off) { r1[tid] += r1[tid + off]; r2[tid] += r2[tid + off]; }
        __syncthreads();
    }
    if (tid == 0) {
        float lse = mx + logf(r1[0]);
        out[0 * BN + b] = sc[pos_action[b]] - lse;
        out[3 * BN + b] = lse - r2[0] / r1[0];
    }
}

// ---------------------------------------------------------------------------
// Kernel C1: sh = relu(X @ W1s + b1s), TWO batches per block (shorter pole),
// grid (32, 4), 256 threads, unroll 8 (latency hiding).
// Per-output k-order identical to 4-batch version -> rel_err unchanged.
// ---------------------------------------------------------------------------
__global__ __launch_bounds__(256) void symbol_h_kernel(
    const float* __restrict__ states, const float* __restrict__ W1s,
    const float* __restrict__ b1s, const int* __restrict__ pos_action)
{
    const int bb = blockIdx.x * 2;
    const int f = blockIdx.y * 256 + threadIdx.x;
    const int tid = threadIdx.x;

    __shared__ float xs[2][KK];
    #pragma unroll
    for (int j = 0; j < 2; ++j) {
        const float* xp = states + (size_t)(bb + j) * SS * EE + (size_t)pos_action[bb + j] * EE;
        for (int i = tid; i < KK; i += 256) xs[j][i] = xp[i];
    }
    __syncthreads();

    const float bias = b1s[f];
    float a0 = bias, a1 = bias;
    #pragma unroll 8
    for (int k = 0; k < KK; ++k) {
        const float wv = W1s[(size_t)k * KK + f];
        a0 = fmaf(xs[0][k], wv, a0);
        a1 = fmaf(xs[1][k], wv, a1);
    }
    g_sh[(bb + 0) * KK + f] = fmaxf(a0, 0.f);
    g_sh[(bb + 1) * KK + f] = fmaxf(a1, 0.f);
}

// ---------------------------------------------------------------------------
// Kernel C2: symbol logits + softmax -> rows 1, 4
// ---------------------------------------------------------------------------
__global__ __launch_bounds__(128) void symbol_logits_kernel(
    const float* __restrict__ W2s, const float* __restrict__ b2s,
    const int* __restrict__ sym_action, float* __restrict__ out)
{
    const int b = blockIdx.x;
    const int tid = threadIdx.x;

    __shared__ float sh[KK];
    __shared__ float lg[AA];
    __shared__ float r1[128], r2[128];

    for (int i = tid; i < KK; i += 128) sh[i] = g_sh[b * KK + i];
    __syncthreads();

    float s = b2s[tid];
    #pragma unroll 8
    for (int k = 0; k < KK; ++k) s = fmaf(sh[k], W2s[(size_t)k * AA + tid], s);
    lg[tid] = s;
    r1[tid] = s;
    __syncthreads();
    for (int off = 64; off > 0; off >>= 1) {
        if (tid < off) r1[tid] = fmaxf(r1[tid], r1[tid + off]);
        __syncthreads();
    }
    const float mx = r1[0];
    __syncthreads();
    float e = expf(lg[tid] - mx);
    r1[tid] = e; r2[tid] = e * lg[tid];
    __syncthreads();
    for (int off = 64; off > 0; off >>= 1) {
        if (tid < off) { r1[tid] += r1[tid + off]; r2[tid] += r2[tid + off]; }
        __syncthreads();
    }
    if (tid == 0) {
        float lse = mx + logf(r1[0]);
        out[1 * BN + b] = lg[sym_action[b]] - lse;
        out[4 * BN + b] = lse - r2[0] / r1[0];
    }
}

// ---------------------------------------------------------------------------
// Kernel D: value head -> row 2. grid 64 (1 batch/block), 256 threads, 2 f each.
// ---------------------------------------------------------------------------
__global__ __launch_bounds__(256) void value_kernel(
    const float* __restrict__ cls, const float* __restrict__ Wc1,
    const float* __restrict__ bc1, const float* __restrict__ wc2,
    const float* __restrict__ bc2, float* __restrict__ out)
{
    const int b = blockIdx.x;
    const int tid = threadIdx.x;

    __shared__ float xs[EE];
    __shared__ float r1[256];

    for (int i = tid; i < EE; i += 256) xs[i] = cls[(size_t)b * EE + i];
    __syncthreads();

    float a0 = bc1[tid], a1 = bc1[tid + 256];
    #pragma unroll 8
    for (int k = 0; k < EE; ++k) {
        const float xk = xs[k];
        const float* wr = Wc1 + (size_t)k * EE;
        a0 = fmaf(xk, wr[tid],       a0);
        a1 = fmaf(xk, wr[tid + 256], a1);
    }
    r1[tid] = fmaxf(a0, 0.f) * wc2[tid] + fmaxf(a1, 0.f) * wc2[tid + 256];
    __syncthreads();
    for (int off = 128; off > 0; off >>= 1) {
        if (tid < off) r1[tid] += r1[tid + off];
        __syncthreads();
    }
    if (tid == 0) out[2 * BN + b] = r1[0] + bc2[0];
}

// ---------------------------------------------------------------------------
extern "C" void kernel_launch(void* const* d_in, const int* in_sizes, int n_in,
                              void* d_out, int out_size)
{
    const float* states     = (const float*)d_in[0];
    const float* cls_token  = (const float*)d_in[1];
    const float* W1p        = (const float*)d_in[2];
    const float* b1p        = (const float*)d_in[3];
    const float* w2p        = (const float*)d_in[4];
    // d_in[5] = b2p : constant shift, cancels in log_softmax
    const float* W1s        = (const float*)d_in[6];
    const float* b1s        = (const float*)d_in[7];
    const float* W2s        = (const float*)d_in[8];
    const float* b2s        = (const float*)d_in[9];
    const float* Wc1        = (const float*)d_in[10];
    const float* bc1        = (const float*)d_in[11];
    const float* wc2        = (const float*)d_in[12];
    const float* bc2        = (const float*)d_in[13];
    const int*   lengths    = (const int*)d_in[14];
    const int*   pos_action = (const int*)d_in[15];
    const int*   sym_action = (const int*)d_in[16];
    float* out = (float*)d_out;

    static int configured = 0;
    static cudaStream_t s1, s2;
    static cudaEvent_t efork, ejoin1, ejoin2;
    if (!configured) {
        cudaFuncSetAttribute(pos_scores_mma, cudaFuncAttributeMaxDynamicSharedMemorySize, DSM_TOTAL);
        cudaStreamCreateWithFlags(&s1, cudaStreamNonBlocking);
        cudaStreamCreateWithFlags(&s2, cudaStreamNonBlocking);
        cudaEventCreateWithFlags(&efork,  cudaEventDisableTiming);
        cudaEventCreateWithFlags(&ejoin1, cudaEventDisableTiming);
        cudaEventCreateWithFlags(&ejoin2, cudaEventDisableTiming);
        configured = 1;
    }

    // fork: side branches depend only on kernel inputs  (R9/R13-proven topology)
    cudaEventRecord(efork, 0);
    cudaStreamWaitEvent(s1, efork, 0);
    cudaStreamWaitEvent(s2, efork, 0);

    // branch s1: symbol head (finer-grained; completes during prep window)
    symbol_h_kernel<<<dim3(32, 4), 256, 0, s1>>>(states, W1s, b1s, pos_action);
    symbol_logits_kernel<<<BN, 128, 0, s1>>>(W2s, b2s, sym_action, out);
    cudaEventRecord(ejoin1, s1);

    // branch s2: value head
    value_kernel<<<BN, 256, 0, s2>>>(cls_token, Wc1, bc1, wc2, bc2, out);
    cudaEventRecord(ejoin2, s2);

    // main branch: merged prep (rowmap + W1pT + states->bf16), GEMM, softmax
    prep_kernel<<<9280, 256>>>(states, W1p, lengths);
    pos_scores_mma<<<512, 256, DSM_TOTAL>>>(b1p, w2p);
    pos_softmax_kernel<<<BN, 256>>>(lengths, pos_action, out);

    // join
    cudaStreamWaitEvent(0, ejoin1, 0);
    cudaStreamWaitEvent(0, ejoin2, 0);
}